// round 16
// baseline (speedup 1.0000x reference)
#include <cuda_runtime.h>
#include <math.h>

#define B_    4
#define N_    8192
#define F_    64
#define NIN_  67
#define NBLK  148
#define TPB   256
#define PPB   224            // points per block; MLP threads = 224 = 7 FULL warps
#define NPTS  (B_ * N_)
#define XS    68             // x-tile row stride in floats (17 float4 chunks)

#define S_OFF 0
#define F_OFF (B_ * N_)
#define C_OFF (B_ * N_ + B_ * N_ * F_)

// ---------------- scratch (no allocations allowed) ----------------
__device__ int               g_nleaf[B_];
__device__ unsigned          g_arrive = 0;
__device__ volatile unsigned g_gen    = 0;

// ---------------- f32x2 helpers ----------------
static __device__ __forceinline__ unsigned long long pack2(float lo, float hi) {
    unsigned long long r;
    asm("mov.b64 %0, {%1, %2};" : "=l"(r) : "f"(lo), "f"(hi));
    return r;
}
static __device__ __forceinline__ void unpack2(unsigned long long v, float& lo, float& hi) {
    asm("mov.b64 {%0, %1}, %2;" : "=f"(lo), "=f"(hi) : "l"(v));
}
static __device__ __forceinline__ unsigned long long ffma2(
    unsigned long long a, unsigned long long b, unsigned long long c) {
    unsigned long long d;
    asm("fma.rn.f32x2 %0, %1, %2, %3;" : "=l"(d) : "l"(a), "l"(b), "l"(c));
    return d;
}

static __device__ __forceinline__ bool read_mask(const void* m, int idx, int mode) {
    if (mode == 1) return ((const int*)m)[idx] != 0;
    if (mode == 2) return ((const float*)m)[idx] != 0.0f;
    return ((const unsigned char*)m)[idx] != 0;
}

// Replay-safe grid-wide barrier (grid == 148 == SM count, 1 block/SM).
static __device__ __forceinline__ void grid_barrier() {
    __syncthreads();
    if (threadIdx.x == 0) {
        unsigned gen = g_gen;
        __threadfence();
        if (atomicAdd(&g_arrive, 1u) == NBLK - 1u) {
            atomicExch(&g_arrive, 0u);
            __threadfence();
            g_gen = gen + 1u;
        } else {
            while (g_gen == gen) __nanosleep(40);
        }
        __threadfence();
    }
    __syncthreads();
}

// dynamic shared: x-tile [PPB][XS] floats during MLP; int index list in finalize
extern __shared__ unsigned char s_raw[];

// ---------------- the single fused kernel ----------------
__global__ void __launch_bounds__(TPB, 1)
fused_kernel(const float* __restrict__ points, const float* __restrict__ features,
             const void* __restrict__ mask,
             const float* __restrict__ W1, const float* __restrict__ b1,
             const float* __restrict__ W2, const float* __restrict__ b2,
             const float* __restrict__ W3, const float* __restrict__ b3,
             float* __restrict__ out) {
    // W1: [j][2q+h] (j=0..67 incl. zero row 67), pairs of neurons h*32+4q..+3
    __shared__ ulonglong2         sW1[(NIN_ + 1) * 16];
    __shared__ unsigned long long sB1[32];
    // W2: [j2][2q2+h], pairs of neurons h*16+4q2..+3
    __shared__ ulonglong2         sW2[64 * 8];
    __shared__ unsigned long long sB2[16];
    __shared__ float              sW3[32];
    __shared__ float              sB3v;
    __shared__ int                s_fl[2];
    __shared__ double sred[8], sred2[8];
    __shared__ int    wsum[8], woff[8];
    __shared__ int    s_cnt;
    __shared__ double bSs, bSs2;

    float* s_x = (float*)s_raw;   // [PPB][XS]

    const int tid  = threadIdx.x;
    const int bid  = blockIdx.x;
    const int lane = tid & 31, wid = tid >> 5;

    // ---- inline mask dtype detection ----
    if (tid < 2) s_fl[tid] = 0;
    __syncthreads();
    {
        unsigned v = ((const unsigned*)mask)[tid & 63];
        if (v > 1u) atomicOr(&s_fl[0], 1);
        if (v != 0u && v != 0x3F800000u) atomicOr(&s_fl[1], 1);
    }

    // ---- stage x-tile: 224 rows x 17 float4 (feat 0..63, then xyz,0) ----
    for (int idx = tid; idx < PPB * 17; idx += TPB) {
        int row = idx / 17, c = idx % 17;
        int pr  = bid * PPB + row;
        int pt  = (pr < NPTS) ? pr : (NPTS - 1);
        float4 v;
        if (c < 16) {
            v = ((const float4*)(features + (size_t)pt * F_))[c];
        } else {
            const float* pp = points + (size_t)pt * 3;
            v = make_float4(pp[0], pp[1], pp[2], 0.0f);
        }
        *(float4*)(s_x + row * XS + 4 * c) = v;
    }

    // ---- weight staging ----
    // W1: (j, q, h) -> sW1[j*16 + 2q + h] = pairs of neurons h*32+4q+{0,1},{2,3}
    for (int idx = tid; idx < (NIN_ + 1) * 16; idx += TPB) {
        int j = idx >> 4, qh = idx & 15;
        int q = qh >> 1, h = qh & 1;
        ulonglong2 w;
        if (j < NIN_) {
            int n0 = h * 32 + 4 * q;
            w.x = pack2(W1[(n0 + 0) * NIN_ + j], W1[(n0 + 1) * NIN_ + j]);
            w.y = pack2(W1[(n0 + 2) * NIN_ + j], W1[(n0 + 3) * NIN_ + j]);
        } else {
            w.x = 0ull; w.y = 0ull;   // zero row for padded input 67
        }
        sW1[idx] = w;
    }
    // W2: (j2, q2, h) -> sW2[j2*8 + 2q2 + h] = pairs of neurons h*16+4q2+{0,1},{2,3}
    for (int idx = tid; idx < 64 * 8; idx += TPB) {
        int j = idx >> 3, qh = idx & 7;
        int q = qh >> 1, h = qh & 1;
        int n0 = h * 16 + 4 * q;
        ulonglong2 w;
        w.x = pack2(W2[(n0 + 0) * 64 + j], W2[(n0 + 1) * 64 + j]);
        w.y = pack2(W2[(n0 + 2) * 64 + j], W2[(n0 + 3) * 64 + j]);
        sW2[idx] = w;
    }
    if (tid < 32) sB1[tid] = pack2(b1[2 * tid], b1[2 * tid + 1]);
    if (tid < 16) sB2[tid] = pack2(b2[2 * tid], b2[2 * tid + 1]);
    if (tid < 32) sW3[tid] = W3[tid];
    if (tid == 0) sB3v = b3[0];

    // ---- feature passthrough copy (all threads) ----
    {
        const float4* src = (const float4*)features;
        float4*       dst = (float4*)(out + F_OFF);
        const int total4 = (B_ * N_ * F_) / 4;
        for (int i = bid * TPB + tid; i < total4; i += NBLK * TPB)
            dst[i] = src[i];
    }
    __syncthreads();
    const int mode = (!s_fl[0]) ? 1 : ((!s_fl[1]) ? 2 : 0);

    // ======== MLP: 2 points per thread, lane-pair neuron split ========
    // half h = tid&1: layer-1 neurons h*32..h*32+31, layer-2 neurons h*16..h*16+15
    // Region = threads 0..223 = warps 0..6 EXACTLY (whole warps only).
    if (tid < PPB) {
        const int  pairL  = (tid >> 1);            // 0..111
        const int  rowA   = 2 * pairL, rowB = rowA + 1;
        const int  prA    = bid * PPB + rowA;
        const int  prB    = bid * PPB + rowB;
        const bool validA = (prA < NPTS), validB = (prB < NPTS);
        const int  ptA    = validA ? prA : (NPTS - 1);
        const int  ptB    = validB ? prB : (NPTS - 1);
        const int  h      = tid & 1;
        const bool mA     = read_mask(mask, ptA, mode);
        const bool mB     = read_mask(mask, ptB, mode);

        float scoreA = 0.0f, scoreB = 0.0f;
        if (__any_sync(0xFFFFFFFFu, (mA && validA) || (mB && validB))) {
            const float* xA = s_x + rowA * XS;
            const float* xB = s_x + rowB * XS;

            unsigned long long accA[16], accB[16];
#pragma unroll
            for (int k = 0; k < 16; k++) { accA[k] = sB1[h * 16 + k]; accB[k] = accA[k]; }

            // ---- layer 1: 17 chunks x 4 inputs (input 67 padded w/ zero row) ----
#pragma unroll
            for (int c = 0; c < 17; c++) {
                float4 vA = *(const float4*)(xA + 4 * c);
                float4 vB = *(const float4*)(xB + 4 * c);
                float xsA[4] = {vA.x, vA.y, vA.z, vA.w};
                float xsB[4] = {vB.x, vB.y, vB.z, vB.w};
#pragma unroll
                for (int u = 0; u < 4; u++) {
                    unsigned long long pA = pack2(xsA[u], xsA[u]);
                    unsigned long long pB = pack2(xsB[u], xsB[u]);
                    const ulonglong2* wrow = &sW1[(4 * c + u) * 16 + h];
#pragma unroll
                    for (int q = 0; q < 8; q++) {
                        ulonglong2 w = wrow[2 * q];      // [j*16 + 2q + h]
                        accA[2 * q]     = ffma2(pA, w.x, accA[2 * q]);
                        accA[2 * q + 1] = ffma2(pA, w.y, accA[2 * q + 1]);
                        accB[2 * q]     = ffma2(pB, w.x, accB[2 * q]);
                        accB[2 * q + 1] = ffma2(pB, w.y, accB[2 * q + 1]);
                    }
                }
            }

            // ---- relu; write this half's h1 into the (now dead) x rows ----
            // row pt, cols h*32 .. h*32+31  (readers/writers = this lane pair only)
#pragma unroll
            for (int q = 0; q < 8; q++) {
                float a0, a1, a2, a3;
                unpack2(accA[2 * q], a0, a1);
                unpack2(accA[2 * q + 1], a2, a3);
                float4 hv = make_float4(fmaxf(a0, 0.f), fmaxf(a1, 0.f),
                                        fmaxf(a2, 0.f), fmaxf(a3, 0.f));
                *(float4*)(s_x + rowA * XS + h * 32 + 4 * q) = hv;
                unpack2(accB[2 * q], a0, a1);
                unpack2(accB[2 * q + 1], a2, a3);
                hv = make_float4(fmaxf(a0, 0.f), fmaxf(a1, 0.f),
                                 fmaxf(a2, 0.f), fmaxf(a3, 0.f));
                *(float4*)(s_x + rowB * XS + h * 32 + 4 * q) = hv;
            }
            __syncwarp(0xFFFFFFFFu);   // pair exchange through shared rows

            // ---- layer 2: 16 quads x 4 inputs ----
            unsigned long long acc2A[8], acc2B[8];
#pragma unroll
            for (int k = 0; k < 8; k++) { acc2A[k] = sB2[h * 8 + k]; acc2B[k] = acc2A[k]; }
#pragma unroll
            for (int Q = 0; Q < 16; Q++) {
                float4 hA = *(const float4*)(s_x + rowA * XS + 4 * Q);
                float4 hB = *(const float4*)(s_x + rowB * XS + 4 * Q);
                float hsA[4] = {hA.x, hA.y, hA.z, hA.w};
                float hsB[4] = {hB.x, hB.y, hB.z, hB.w};
#pragma unroll
                for (int u = 0; u < 4; u++) {
                    unsigned long long pA = pack2(hsA[u], hsA[u]);
                    unsigned long long pB = pack2(hsB[u], hsB[u]);
                    const ulonglong2* wrow = &sW2[(4 * Q + u) * 8 + h];
#pragma unroll
                    for (int q = 0; q < 4; q++) {
                        ulonglong2 w = wrow[2 * q];      // [j2*8 + 2q2 + h]
                        acc2A[2 * q]     = ffma2(pA, w.x, acc2A[2 * q]);
                        acc2A[2 * q + 1] = ffma2(pA, w.y, acc2A[2 * q + 1]);
                        acc2B[2 * q]     = ffma2(pB, w.x, acc2B[2 * q]);
                        acc2B[2 * q + 1] = ffma2(pB, w.y, acc2B[2 * q + 1]);
                    }
                }
            }

            // ---- layer 3 partials over this half's 16 layer-2 neurons ----
            float zA = 0.0f, zB = 0.0f;
#pragma unroll
            for (int q = 0; q < 4; q++) {
                float l0, h0, l1, h1v;
                int n = h * 16 + 4 * q;
                unpack2(acc2A[2 * q], l0, h0);
                unpack2(acc2A[2 * q + 1], l1, h1v);
                zA += fmaxf(l0, 0.f) * sW3[n]     + fmaxf(h0, 0.f)  * sW3[n + 1]
                    + fmaxf(l1, 0.f) * sW3[n + 2] + fmaxf(h1v, 0.f) * sW3[n + 3];
                unpack2(acc2B[2 * q], l0, h0);
                unpack2(acc2B[2 * q + 1], l1, h1v);
                zB += fmaxf(l0, 0.f) * sW3[n]     + fmaxf(h0, 0.f)  * sW3[n + 1]
                    + fmaxf(l1, 0.f) * sW3[n + 2] + fmaxf(h1v, 0.f) * sW3[n + 3];
            }
            zA += __shfl_xor_sync(0xFFFFFFFFu, zA, 1);
            zB += __shfl_xor_sync(0xFFFFFFFFu, zB, 1);
            zA += sB3v; zB += sB3v;
            scoreA = 1.0f / (1.0f + expf(-zA));
            scoreB = 1.0f / (1.0f + expf(-zB));
        }
        if (h == 0) { if (validA) out[S_OFF + ptA] = mA ? scoreA : 0.0f; }
        else        { if (validB) out[S_OFF + ptB] = mB ? scoreB : 0.0f; }
    }

    // ---- pre-barrier n_leaf: blocks 144..147 handle batch bid-144 ----
    if (bid >= NBLK - B_) {
        const int b = bid - (NBLK - B_);
        int lc = 0;
#pragma unroll
        for (int k = 0; k < 32; k++)
            lc += read_mask(mask, b * N_ + tid * 32 + k, mode) ? 1 : 0;
#pragma unroll
        for (int o = 16; o > 0; o >>= 1) lc += __shfl_down_sync(0xFFFFFFFFu, lc, o);
        if (lane == 0) wsum[wid] = lc;
        __syncthreads();
        if (tid == 0) {
            int s = 0;
#pragma unroll
            for (int w = 0; w < 8; w++) s += wsum[w];
            g_nleaf[b] = s;
        }
    }

    // ================= grid-wide barrier =================
    grid_barrier();

    if (bid >= B_) return;

    // ================= finalize: batch b = bid =================
    int* s_dyn = (int*)s_raw;   // x-tile dead; reuse as index list
    const int    b      = bid;
    float*       scores = out + S_OFF + b * N_;
    const float* pts    = points + (size_t)b * N_ * 3;
    const int n_leaf = *(volatile int*)&g_nleaf[b];

    float sv[32];
    {
        const float4* s4 = (const float4*)scores + tid * 8;
#pragma unroll
        for (int q = 0; q < 8; q++) {
            float4 v = s4[q];
            sv[4 * q + 0] = v.x; sv[4 * q + 1] = v.y;
            sv[4 * q + 2] = v.z; sv[4 * q + 3] = v.w;
        }
    }
    const float zfac = (n_leaf < 10) ? 0.0f : 1.0f;
    double ls = 0.0, ls2 = 0.0;
#pragma unroll
    for (int k = 0; k < 32; k++) {
        float s = sv[k] * zfac;
        sv[k] = s;
        ls += s; ls2 += (double)s * (double)s;
    }
    if (n_leaf < 10) {
        float4 z4 = make_float4(0.f, 0.f, 0.f, 0.f);
        float4* s4 = (float4*)scores + tid * 8;
#pragma unroll
        for (int q = 0; q < 8; q++) s4[q] = z4;
    }
#pragma unroll
    for (int o = 16; o > 0; o >>= 1) {
        ls  += __shfl_down_sync(0xFFFFFFFFu, ls, o);
        ls2 += __shfl_down_sync(0xFFFFFFFFu, ls2, o);
    }
    if (lane == 0) { sred[wid] = ls; sred2[wid] = ls2; }
    __syncthreads();
    if (tid == 0) {
        double a = 0.0, c = 0.0;
#pragma unroll
        for (int w = 0; w < 8; w++) { a += sred[w]; c += sred2[w]; }
        bSs = a; bSs2 = c;
    }
    __syncthreads();

    int c = 0;
#pragma unroll
    for (int k = 0; k < 32; k++) c += (sv[k] > 0.7f) ? 1 : 0;
    int incl = c;
#pragma unroll
    for (int o = 1; o < 32; o <<= 1) {
        int t = __shfl_up_sync(0xFFFFFFFFu, incl, o);
        if (lane >= o) incl += t;
    }
    if (lane == 31) wsum[wid] = incl;
    __syncthreads();
    if (tid == 0) {
        int run = 0;
#pragma unroll
        for (int w = 0; w < 8; w++) { int t = wsum[w]; woff[w] = run; run += t; }
        s_cnt = run;
    }
    __syncthreads();
    int       pos = incl - c + woff[wid];
    const int cnt = s_cnt;
#pragma unroll
    for (int k = 0; k < 32; k++) {
        if (sv[k] > 0.7f) s_dyn[pos++] = tid * 32 + k;
    }
    __syncthreads();

    double ld = 0.0, ld2 = 0.0;
    for (int k = tid; k < cnt - 1; k += TPB) {
        int i0 = s_dyn[k], i1 = s_dyn[k + 1];
        float dx = pts[i1 * 3 + 0] - pts[i0 * 3 + 0];
        float dy = pts[i1 * 3 + 1] - pts[i0 * 3 + 1];
        float dz = pts[i1 * 3 + 2] - pts[i0 * 3 + 2];
        float dd = sqrtf(dx * dx + dy * dy + dz * dz);
        ld += dd; ld2 += (double)dd * (double)dd;
    }
#pragma unroll
    for (int o = 16; o > 0; o >>= 1) {
        ld  += __shfl_down_sync(0xFFFFFFFFu, ld, o);
        ld2 += __shfl_down_sync(0xFFFFFFFFu, ld2, o);
    }
    if (lane == 0) { sred[wid] = ld; sred2[wid] = ld2; }
    __syncthreads();
    if (tid == 0) {
        double Sd = 0.0, Sd2 = 0.0;
#pragma unroll
        for (int w = 0; w < 8; w++) { Sd += sred[w]; Sd2 += sred2[w]; }

        const double Ss = bSs, Ss2 = bSs2;
        double nl    = (double)n_leaf;
        double meanS = Ss / fmax(nl, 1.0);
        float  clarity = (float)((Ss2 - nl * meanS * meanS) / fmax(nl - 1.0, 1.0));
        int np = cnt - 1; if (np < 0) np = 0;
        double dnp   = (double)np;
        double meanD = Sd / fmax(dnp, 1.0);
        float  dvar  = (float)((Sd2 - dnp * meanD * meanD) / fmax(dnp - 1.0, 1.0));
        float cont = 1.0f / (dvar + 1e-8f);
        cont = fminf(fmaxf(cont, 0.0f), 1.0f);
        if (!(cnt > 5)) cont = 0.0f;
        float conf = fminf(fmaxf(clarity * cont, 0.0f), 1.0f);
        if (n_leaf == 0) conf = 0.0f;
        out[C_OFF + b] = conf;
    }
}

// ---------------- launch ----------------
extern "C" void kernel_launch(void* const* d_in, const int* in_sizes, int n_in,
                              void* d_out, int out_size) {
    const float* points   = (const float*)d_in[0];
    const float* features = (const float*)d_in[1];
    const void*  mask     = d_in[2];
    const float* W1 = (const float*)d_in[3];
    const float* b1 = (const float*)d_in[4];
    const float* W2 = (const float*)d_in[5];
    const float* b2 = (const float*)d_in[6];
    const float* W3 = (const float*)d_in[7];
    const float* b3 = (const float*)d_in[8];
    float* out = (float*)d_out;

    const int dyn = PPB * XS * (int)sizeof(float);   // 60928 B (> finalize's 32KB)
    cudaFuncSetAttribute(fused_kernel,
                         cudaFuncAttributeMaxDynamicSharedMemorySize, dyn);
    fused_kernel<<<NBLK, TPB, dyn>>>(points, features, mask,
                                     W1, b1, W2, b2, W3, b3, out);
}

// round 17
// speedup vs baseline: 1.0066x; 1.0066x over previous
#include <cuda_runtime.h>
#include <math.h>

#define B_    4
#define N_    8192
#define F_    64
#define NIN_  67
#define NBLK  148
#define TPB   512
#define PPB   224            // points per block; MLP threads = 448 = 14 FULL warps
#define MLPT  448
#define NPTS  (B_ * N_)
#define XS    68             // x-tile row stride in floats (17 float4 chunks)

#define S_OFF 0
#define F_OFF (B_ * N_)
#define C_OFF (B_ * N_ + B_ * N_ * F_)

// ---------------- scratch (no allocations allowed) ----------------
__device__ int               g_nleaf[B_];
__device__ unsigned          g_arrive = 0;
__device__ volatile unsigned g_gen    = 0;

// ---------------- f32x2 helpers ----------------
static __device__ __forceinline__ unsigned long long pack2(float lo, float hi) {
    unsigned long long r;
    asm("mov.b64 %0, {%1, %2};" : "=l"(r) : "f"(lo), "f"(hi));
    return r;
}
static __device__ __forceinline__ void unpack2(unsigned long long v, float& lo, float& hi) {
    asm("mov.b64 {%0, %1}, %2;" : "=f"(lo), "=f"(hi) : "l"(v));
}
static __device__ __forceinline__ unsigned long long ffma2(
    unsigned long long a, unsigned long long b, unsigned long long c) {
    unsigned long long d;
    asm("fma.rn.f32x2 %0, %1, %2, %3;" : "=l"(d) : "l"(a), "l"(b), "l"(c));
    return d;
}

static __device__ __forceinline__ bool read_mask(const void* m, int idx, int mode) {
    if (mode == 1) return ((const int*)m)[idx] != 0;
    if (mode == 2) return ((const float*)m)[idx] != 0.0f;
    return ((const unsigned char*)m)[idx] != 0;
}

// Replay-safe grid-wide barrier (grid == 148 == SM count, 1 block/SM).
static __device__ __forceinline__ void grid_barrier() {
    __syncthreads();
    if (threadIdx.x == 0) {
        unsigned gen = g_gen;
        __threadfence();
        if (atomicAdd(&g_arrive, 1u) == NBLK - 1u) {
            atomicExch(&g_arrive, 0u);
            __threadfence();
            g_gen = gen + 1u;
        } else {
            while (g_gen == gen) __nanosleep(40);
        }
        __threadfence();
    }
    __syncthreads();
}

// dynamic shared: x-tile [PPB][XS] floats during MLP; int index list in finalize
extern __shared__ unsigned char s_raw[];

// ---------------- the single fused kernel ----------------
__global__ void __launch_bounds__(TPB, 1)
fused_kernel(const float* __restrict__ points, const float* __restrict__ features,
             const void* __restrict__ mask,
             const float* __restrict__ W1, const float* __restrict__ b1,
             const float* __restrict__ W2, const float* __restrict__ b2,
             const float* __restrict__ W3, const float* __restrict__ b3,
             float* __restrict__ out) {
    // W1: [j][4q + h], h=lane&3: neurons h*16+4q..+3 as 2 f32x2 (j=67 zero row)
    __shared__ ulonglong2         sW1[(NIN_ + 1) * 16];
    __shared__ unsigned long long sB1[32];
    // W2: [j2][2h + t]: neurons h*8+4t..+3 as 2 f32x2
    __shared__ ulonglong2         sW2[64 * 8];
    __shared__ unsigned long long sB2[16];
    __shared__ float              sW3[32];
    __shared__ float              sB3v;
    __shared__ int                s_fl[2];
    __shared__ double sred[16], sred2[16];
    __shared__ int    wsum[16], woff[16];
    __shared__ int    s_cnt;
    __shared__ double bSs, bSs2;

    float* s_x = (float*)s_raw;   // [PPB][XS]

    const int tid  = threadIdx.x;
    const int bid  = blockIdx.x;
    const int lane = tid & 31, wid = tid >> 5;

    // ---- inline mask dtype detection ----
    if (tid < 2) s_fl[tid] = 0;
    __syncthreads();
    {
        unsigned v = ((const unsigned*)mask)[tid & 63];
        if (v > 1u) atomicOr(&s_fl[0], 1);
        if (v != 0u && v != 0x3F800000u) atomicOr(&s_fl[1], 1);
    }

    // ---- stage x-tile: 224 rows x 17 float4 (feat 0..63, then xyz,0) ----
    for (int idx = tid; idx < PPB * 17; idx += TPB) {
        int row = idx / 17, c = idx % 17;
        int pr  = bid * PPB + row;
        int pt  = (pr < NPTS) ? pr : (NPTS - 1);
        float4 v;
        if (c < 16) {
            v = ((const float4*)(features + (size_t)pt * F_))[c];
        } else {
            const float* pp = points + (size_t)pt * 3;
            v = make_float4(pp[0], pp[1], pp[2], 0.0f);
        }
        *(float4*)(s_x + row * XS + 4 * c) = v;
    }

    // ---- weight staging ----
    // sW1[j*16 + 4q + h] = neurons h*16+4q+{0..3}
    for (int idx = tid; idx < (NIN_ + 1) * 16; idx += TPB) {
        int j = idx >> 4, r = idx & 15;
        int q = r >> 2, h = r & 3;
        ulonglong2 w;
        if (j < NIN_) {
            int n0 = h * 16 + 4 * q;
            w.x = pack2(W1[(n0 + 0) * NIN_ + j], W1[(n0 + 1) * NIN_ + j]);
            w.y = pack2(W1[(n0 + 2) * NIN_ + j], W1[(n0 + 3) * NIN_ + j]);
        } else {
            w.x = 0ull; w.y = 0ull;   // zero row for padded input 67
        }
        sW1[idx] = w;
    }
    // sW2[j*8 + 2h + t] = neurons h*8+4t+{0..3}
    for (int idx = tid; idx < 64 * 8; idx += TPB) {
        int j = idx >> 3, r = idx & 7;
        int h = r >> 1, t = r & 1;
        int n0 = h * 8 + 4 * t;
        ulonglong2 w;
        w.x = pack2(W2[(n0 + 0) * 64 + j], W2[(n0 + 1) * 64 + j]);
        w.y = pack2(W2[(n0 + 2) * 64 + j], W2[(n0 + 3) * 64 + j]);
        sW2[idx] = w;
    }
    if (tid < 32) sB1[tid] = pack2(b1[2 * tid], b1[2 * tid + 1]);
    if (tid < 16) sB2[tid] = pack2(b2[2 * tid], b2[2 * tid + 1]);
    if (tid < 32) sW3[tid] = W3[tid];
    if (tid == 0) sB3v = b3[0];

    // ---- feature passthrough copy: 7-deep batched loads (all threads) ----
    {
        const float4* src = (const float4*)features;
        float4*       dst = (float4*)(out + F_OFF);
        const int total4 = (B_ * N_ * F_) / 4;      // 524288
        const int stride = NBLK * TPB;              // 75776
        const int i0 = bid * TPB + tid;
        float4 v[7];
#pragma unroll
        for (int k = 0; k < 7; k++) {
            int idx = i0 + k * stride;
            if (idx < total4) v[k] = src[idx];
        }
#pragma unroll
        for (int k = 0; k < 7; k++) {
            int idx = i0 + k * stride;
            if (idx < total4) dst[idx] = v[k];
        }
    }
    __syncthreads();
    const int mode = (!s_fl[0]) ? 1 : ((!s_fl[1]) ? 2 : 0);

    // ======== MLP: lane-QUAD handles 2 points, 4-way neuron split ========
    // h = tid&3: layer-1 neurons h*16..h*16+15, layer-2 neurons h*8..h*8+7
    // Region = threads 0..447 = warps 0..13 EXACTLY (whole warps only).
    if (tid < MLPT) {
        const int  quad   = tid >> 2;              // 0..111
        const int  rowA   = 2 * quad, rowB = rowA + 1;
        const int  prA    = bid * PPB + rowA;
        const int  prB    = bid * PPB + rowB;
        const bool validA = (prA < NPTS), validB = (prB < NPTS);
        const int  ptA    = validA ? prA : (NPTS - 1);
        const int  ptB    = validB ? prB : (NPTS - 1);
        const int  h      = tid & 3;
        const bool mA     = read_mask(mask, ptA, mode);
        const bool mB     = read_mask(mask, ptB, mode);

        float scoreA = 0.0f, scoreB = 0.0f;
        if (__any_sync(0xFFFFFFFFu, (mA && validA) || (mB && validB))) {
            const float* xA = s_x + rowA * XS;
            const float* xB = s_x + rowB * XS;

            unsigned long long accA[8], accB[8];
#pragma unroll
            for (int k = 0; k < 8; k++) { accA[k] = sB1[h * 8 + k]; accB[k] = accA[k]; }

            // ---- layer 1: 17 chunks x 4 inputs; per u: 4 LDS.128 -> 16 FFMA2 ----
#pragma unroll
            for (int c = 0; c < 17; c++) {
                float4 vA = *(const float4*)(xA + 4 * c);
                float4 vB = *(const float4*)(xB + 4 * c);
                float xsA[4] = {vA.x, vA.y, vA.z, vA.w};
                float xsB[4] = {vB.x, vB.y, vB.z, vB.w};
#pragma unroll
                for (int u = 0; u < 4; u++) {
                    unsigned long long pA = pack2(xsA[u], xsA[u]);
                    unsigned long long pB = pack2(xsB[u], xsB[u]);
                    const ulonglong2* wrow = &sW1[(4 * c + u) * 16 + h];
#pragma unroll
                    for (int q = 0; q < 4; q++) {
                        ulonglong2 w = wrow[4 * q];      // [j*16 + 4q + h]
                        accA[2 * q]     = ffma2(pA, w.x, accA[2 * q]);
                        accA[2 * q + 1] = ffma2(pA, w.y, accA[2 * q + 1]);
                        accB[2 * q]     = ffma2(pB, w.x, accB[2 * q]);
                        accB[2 * q + 1] = ffma2(pB, w.y, accB[2 * q + 1]);
                    }
                }
            }

            // ---- relu; write this quarter's h1 into the dead x rows ----
            // row, cols h*16 .. h*16+15 (owner = this lane quad only)
#pragma unroll
            for (int q = 0; q < 4; q++) {
                float a0, a1, a2, a3;
                unpack2(accA[2 * q], a0, a1);
                unpack2(accA[2 * q + 1], a2, a3);
                *(float4*)(s_x + rowA * XS + h * 16 + 4 * q) =
                    make_float4(fmaxf(a0, 0.f), fmaxf(a1, 0.f),
                                fmaxf(a2, 0.f), fmaxf(a3, 0.f));
                unpack2(accB[2 * q], a0, a1);
                unpack2(accB[2 * q + 1], a2, a3);
                *(float4*)(s_x + rowB * XS + h * 16 + 4 * q) =
                    make_float4(fmaxf(a0, 0.f), fmaxf(a1, 0.f),
                                fmaxf(a2, 0.f), fmaxf(a3, 0.f));
            }
            __syncwarp(0xFFFFFFFFu);   // quad exchange through shared rows

            // ---- layer 2: 16 quads x 4 inputs; per u: 2 LDS.128 -> 8 FFMA2 ----
            unsigned long long acc2A[4], acc2B[4];
#pragma unroll
            for (int k = 0; k < 4; k++) { acc2A[k] = sB2[h * 4 + k]; acc2B[k] = acc2A[k]; }
#pragma unroll
            for (int Q = 0; Q < 16; Q++) {
                float4 hA = *(const float4*)(s_x + rowA * XS + 4 * Q);
                float4 hB = *(const float4*)(s_x + rowB * XS + 4 * Q);
                float hsA[4] = {hA.x, hA.y, hA.z, hA.w};
                float hsB[4] = {hB.x, hB.y, hB.z, hB.w};
#pragma unroll
                for (int u = 0; u < 4; u++) {
                    unsigned long long pA = pack2(hsA[u], hsA[u]);
                    unsigned long long pB = pack2(hsB[u], hsB[u]);
                    const ulonglong2* wrow = &sW2[(4 * Q + u) * 8 + 2 * h];
#pragma unroll
                    for (int t = 0; t < 2; t++) {
                        ulonglong2 w = wrow[t];          // [j2*8 + 2h + t]
                        acc2A[2 * t]     = ffma2(pA, w.x, acc2A[2 * t]);
                        acc2A[2 * t + 1] = ffma2(pA, w.y, acc2A[2 * t + 1]);
                        acc2B[2 * t]     = ffma2(pB, w.x, acc2B[2 * t]);
                        acc2B[2 * t + 1] = ffma2(pB, w.y, acc2B[2 * t + 1]);
                    }
                }
            }

            // ---- layer 3 partials over this quarter's 8 layer-2 neurons ----
            float zA = 0.0f, zB = 0.0f;
#pragma unroll
            for (int t = 0; t < 2; t++) {
                float l0, h0, l1, h1v;
                int n = h * 8 + 4 * t;
                unpack2(acc2A[2 * t], l0, h0);
                unpack2(acc2A[2 * t + 1], l1, h1v);
                zA += fmaxf(l0, 0.f) * sW3[n]     + fmaxf(h0, 0.f)  * sW3[n + 1]
                    + fmaxf(l1, 0.f) * sW3[n + 2] + fmaxf(h1v, 0.f) * sW3[n + 3];
                unpack2(acc2B[2 * t], l0, h0);
                unpack2(acc2B[2 * t + 1], l1, h1v);
                zB += fmaxf(l0, 0.f) * sW3[n]     + fmaxf(h0, 0.f)  * sW3[n + 1]
                    + fmaxf(l1, 0.f) * sW3[n + 2] + fmaxf(h1v, 0.f) * sW3[n + 3];
            }
            // reduce across the lane quad
            zA += __shfl_xor_sync(0xFFFFFFFFu, zA, 1);
            zA += __shfl_xor_sync(0xFFFFFFFFu, zA, 2);
            zB += __shfl_xor_sync(0xFFFFFFFFu, zB, 1);
            zB += __shfl_xor_sync(0xFFFFFFFFu, zB, 2);
            zA += sB3v; zB += sB3v;
            scoreA = 1.0f / (1.0f + expf(-zA));
            scoreB = 1.0f / (1.0f + expf(-zB));
        }
        if (h == 0)      { if (validA) out[S_OFF + ptA] = mA ? scoreA : 0.0f; }
        else if (h == 1) { if (validB) out[S_OFF + ptB] = mB ? scoreB : 0.0f; }
    }

    // ---- pre-barrier n_leaf: blocks 144..147 handle batch bid-144 ----
    if (bid >= NBLK - B_) {
        const int b = bid - (NBLK - B_);
        int lc = 0;
#pragma unroll
        for (int k = 0; k < 16; k++)
            lc += read_mask(mask, b * N_ + tid * 16 + k, mode) ? 1 : 0;
#pragma unroll
        for (int o = 16; o > 0; o >>= 1) lc += __shfl_down_sync(0xFFFFFFFFu, lc, o);
        if (lane == 0) wsum[wid] = lc;
        __syncthreads();
        if (tid == 0) {
            int s = 0;
#pragma unroll
            for (int w = 0; w < 16; w++) s += wsum[w];
            g_nleaf[b] = s;
        }
    }

    // ================= grid-wide barrier =================
    grid_barrier();

    if (bid >= B_) return;

    // ================= finalize: batch b = bid, 512 threads =================
    int* s_dyn = (int*)s_raw;   // x-tile dead; reuse as index list
    const int    b      = bid;
    float*       scores = out + S_OFF + b * N_;
    const float* pts    = points + (size_t)b * N_ * 3;
    const int n_leaf = *(volatile int*)&g_nleaf[b];

    float sv[16];
    {
        const float4* s4 = (const float4*)scores + tid * 4;
#pragma unroll
        for (int q = 0; q < 4; q++) {
            float4 v = s4[q];
            sv[4 * q + 0] = v.x; sv[4 * q + 1] = v.y;
            sv[4 * q + 2] = v.z; sv[4 * q + 3] = v.w;
        }
    }
    const float zfac = (n_leaf < 10) ? 0.0f : 1.0f;
    double ls = 0.0, ls2 = 0.0;
#pragma unroll
    for (int k = 0; k < 16; k++) {
        float s = sv[k] * zfac;
        sv[k] = s;
        ls += s; ls2 += (double)s * (double)s;
    }
    if (n_leaf < 10) {
        float4 z4 = make_float4(0.f, 0.f, 0.f, 0.f);
        float4* s4 = (float4*)scores + tid * 4;
#pragma unroll
        for (int q = 0; q < 4; q++) s4[q] = z4;
    }
#pragma unroll
    for (int o = 16; o > 0; o >>= 1) {
        ls  += __shfl_down_sync(0xFFFFFFFFu, ls, o);
        ls2 += __shfl_down_sync(0xFFFFFFFFu, ls2, o);
    }
    if (lane == 0) { sred[wid] = ls; sred2[wid] = ls2; }
    __syncthreads();
    if (tid == 0) {
        double a = 0.0, c = 0.0;
#pragma unroll
        for (int w = 0; w < 16; w++) { a += sred[w]; c += sred2[w]; }
        bSs = a; bSs2 = c;
    }
    __syncthreads();

    int c = 0;
#pragma unroll
    for (int k = 0; k < 16; k++) c += (sv[k] > 0.7f) ? 1 : 0;
    int incl = c;
#pragma unroll
    for (int o = 1; o < 32; o <<= 1) {
        int t = __shfl_up_sync(0xFFFFFFFFu, incl, o);
        if (lane >= o) incl += t;
    }
    if (lane == 31) wsum[wid] = incl;
    __syncthreads();
    if (tid == 0) {
        int run = 0;
#pragma unroll
        for (int w = 0; w < 16; w++) { int t = wsum[w]; woff[w] = run; run += t; }
        s_cnt = run;
    }
    __syncthreads();
    int       pos = incl - c + woff[wid];
    const int cnt = s_cnt;
#pragma unroll
    for (int k = 0; k < 16; k++) {
        if (sv[k] > 0.7f) s_dyn[pos++] = tid * 16 + k;
    }
    __syncthreads();

    double ld = 0.0, ld2 = 0.0;
    for (int k = tid; k < cnt - 1; k += TPB) {
        int i0 = s_dyn[k], i1 = s_dyn[k + 1];
        float dx = pts[i1 * 3 + 0] - pts[i0 * 3 + 0];
        float dy = pts[i1 * 3 + 1] - pts[i0 * 3 + 1];
        float dz = pts[i1 * 3 + 2] - pts[i0 * 3 + 2];
        float dd = sqrtf(dx * dx + dy * dy + dz * dz);
        ld += dd; ld2 += (double)dd * (double)dd;
    }
#pragma unroll
    for (int o = 16; o > 0; o >>= 1) {
        ld  += __shfl_down_sync(0xFFFFFFFFu, ld, o);
        ld2 += __shfl_down_sync(0xFFFFFFFFu, ld2, o);
    }
    if (lane == 0) { sred[wid] = ld; sred2[wid] = ld2; }
    __syncthreads();
    if (tid == 0) {
        double Sd = 0.0, Sd2 = 0.0;
#pragma unroll
        for (int w = 0; w < 16; w++) { Sd += sred[w]; Sd2 += sred2[w]; }

        const double Ss = bSs, Ss2 = bSs2;
        double nl    = (double)n_leaf;
        double meanS = Ss / fmax(nl, 1.0);
        float  clarity = (float)((Ss2 - nl * meanS * meanS) / fmax(nl - 1.0, 1.0));
        int np = cnt - 1; if (np < 0) np = 0;
        double dnp   = (double)np;
        double meanD = Sd / fmax(dnp, 1.0);
        float  dvar  = (float)((Sd2 - dnp * meanD * meanD) / fmax(dnp - 1.0, 1.0));
        float cont = 1.0f / (dvar + 1e-8f);
        cont = fminf(fmaxf(cont, 0.0f), 1.0f);
        if (!(cnt > 5)) cont = 0.0f;
        float conf = fminf(fmaxf(clarity * cont, 0.0f), 1.0f);
        if (n_leaf == 0) conf = 0.0f;
        out[C_OFF + b] = conf;
    }
}

// ---------------- launch ----------------
extern "C" void kernel_launch(void* const* d_in, const int* in_sizes, int n_in,
                              void* d_out, int out_size) {
    const float* points   = (const float*)d_in[0];
    const float* features = (const float*)d_in[1];
    const void*  mask     = d_in[2];
    const float* W1 = (const float*)d_in[3];
    const float* b1 = (const float*)d_in[4];
    const float* W2 = (const float*)d_in[5];
    const float* b2 = (const float*)d_in[6];
    const float* W3 = (const float*)d_in[7];
    const float* b3 = (const float*)d_in[8];
    float* out = (float*)d_out;

    const int dyn = PPB * XS * (int)sizeof(float);   // 60928 B
    cudaFuncSetAttribute(fused_kernel,
                         cudaFuncAttributeMaxDynamicSharedMemorySize, dyn);
    fused_kernel<<<NBLK, TPB, dyn>>>(points, features, mask,
                                     W1, b1, W2, b2, W3, b3, out);
}